// round 7
// baseline (speedup 1.0000x reference)
#include <cuda_runtime.h>
#include <math.h>
#include <stdint.h>

// ---------------- constants ----------------
#define TEMP      0.07f
#define INV_TEMP  (1.0f / 0.07f)
#define MOMENTUM  0.2f
#define KSEL      1024
#define NEPS      1e-12f

#define GB 64
#define GN 16384
#define GD 2048

// GEMM tile: 64(M=B) x 128(N) x 32(K), 128 threads, 8x8 micro-tile
#define BN2 128
#define BK2 32
#define LDA 68    // smem row stride (floats) for A (K-major)
#define LDB 132   // smem row stride (floats) for B (K-major)

#define TPK_THREADS 512
#define CAP 8192

// dynamic smem layout for topk kernel
#define OFF_KEYS  0
#define OFF_CAND0 65536
#define OFF_CAND1 (65536 + 32768)
#define OFF_WHIST (65536 + 65536)
#define TPK_SMEM  (OFF_WHIST + 16384)

// ---------------- scratch ----------------
static __device__ float g_mat[GB * GN];   // [B][N] similarity matrix
static __device__ float g_loss[GB];
static __device__ unsigned g_cnt = 0;

// ---------------- helpers ----------------
__device__ __forceinline__ void fma2(unsigned long long &d, unsigned long long a, unsigned long long b) {
    asm("fma.rn.f32x2 %0, %1, %2, %0;" : "+l"(d) : "l"(a), "l"(b));
}
__device__ __forceinline__ unsigned long long splat2(float x) {
    unsigned long long r;
    asm("mov.b64 %0, {%1, %1};" : "=l"(r) : "f"(x));
    return r;
}
__device__ __forceinline__ float keyval(unsigned k) {
    unsigned u = (k & 0x80000000u) ? (k & 0x7fffffffu) : ~k;
    return __uint_as_float(u);
}
__device__ __forceinline__ float wred_add(float v) {
#pragma unroll
    for (int o = 16; o > 0; o >>= 1) v += __shfl_xor_sync(0xffffffffu, v, o);
    return v;
}
__device__ __forceinline__ float wred_min(float v) {
#pragma unroll
    for (int o = 16; o > 0; o >>= 1) v = fminf(v, __shfl_xor_sync(0xffffffffu, v, o));
    return v;
}
__device__ __forceinline__ float wred_max(float v) {
#pragma unroll
    for (int o = 16; o > 0; o >>= 1) v = fmaxf(v, __shfl_xor_sync(0xffffffffu, v, o));
    return v;
}

// ---------------- GEMM (64 x N x D) fused with features->out copy ----------------
// grid = GN/BN2 = 128 CTAs, 128 threads, 8x8 micro-tile via packed f32x2 FMA.
// NOTE: outF is (d_out + 1 float) => only 4-byte aligned. ALL stores to outF
// must be scalar 32-bit stores.
extern "C" __global__ void __launch_bounds__(128)
gemm_copy_kernel(const float* __restrict__ f, const float* __restrict__ feat,
                 float* __restrict__ outF, int N, int D)
{
    __shared__ float As[BK2 * LDA];
    __shared__ float Bs[BK2 * LDB];

    const int tid = threadIdx.x;
    const int tx  = tid & 15;     // n direction (8 cols each)
    const int ty  = tid >> 4;     // m direction (8 rows each)
    const int n0  = blockIdx.x * BN2;
    const int nK  = D / BK2;

    unsigned long long acc[8][4];
#pragma unroll
    for (int i = 0; i < 8; i++)
#pragma unroll
        for (int j = 0; j < 4; j++) acc[i][j] = 0ull;

    // loader mapping: row = tid>>3 (0..15), kq = tid&7 (8 float4 per 32-float row)
    const int lrow = tid >> 3;
    const int lkq  = tid & 7;

    const float* gA = f    + (size_t)lrow        * D + lkq * 4;    // rows lrow + 16*i, i<4
    const float* gB = feat + (size_t)(n0 + lrow) * D + lkq * 4;    // rows lrow + 16*i, i<8

    float4 ra[4];
    float4 rb[8];
#pragma unroll
    for (int i = 0; i < 4; i++) ra[i] = *(const float4*)(gA + (size_t)(16 * i) * D);
#pragma unroll
    for (int i = 0; i < 8; i++) rb[i] = *(const float4*)(gB + (size_t)(16 * i) * D);

    for (int kt = 0; kt < nK; kt++) {
        // stage current tile into smem (K-major) + stream B tile to outF (copy fusion)
        {
            const int c0 = lkq * 4;
#pragma unroll
            for (int i = 0; i < 4; i++) {
                const int r = lrow + 16 * i;
                As[(c0 + 0) * LDA + r] = ra[i].x;
                As[(c0 + 1) * LDA + r] = ra[i].y;
                As[(c0 + 2) * LDA + r] = ra[i].z;
                As[(c0 + 3) * LDA + r] = ra[i].w;
            }
#pragma unroll
            for (int i = 0; i < 8; i++) {
                const int r = lrow + 16 * i;
                Bs[(c0 + 0) * LDB + r] = rb[i].x;
                Bs[(c0 + 1) * LDB + r] = rb[i].y;
                Bs[(c0 + 2) * LDB + r] = rb[i].z;
                Bs[(c0 + 3) * LDB + r] = rb[i].w;
                // scalar stores: outF is only 4-byte aligned
                float* o = outF + (size_t)(n0 + r) * D + (size_t)kt * BK2 + c0;
                o[0] = rb[i].x; o[1] = rb[i].y; o[2] = rb[i].z; o[3] = rb[i].w;
            }
        }
        __syncthreads();

        // prefetch next tile into registers (hidden under compute)
        if (kt + 1 < nK) {
            const int off = (kt + 1) * BK2;
#pragma unroll
            for (int i = 0; i < 4; i++) ra[i] = *(const float4*)(gA + (size_t)(16 * i) * D + off);
#pragma unroll
            for (int i = 0; i < 8; i++) rb[i] = *(const float4*)(gB + (size_t)(16 * i) * D + off);
        }

#pragma unroll
        for (int kk = 0; kk < BK2; kk++) {
            float4 a0 = *(const float4*)&As[kk * LDA + ty * 8];
            float4 a1 = *(const float4*)&As[kk * LDA + ty * 8 + 4];
            float4 b0 = *(const float4*)&Bs[kk * LDB + tx * 8];
            float4 b1 = *(const float4*)&Bs[kk * LDB + tx * 8 + 4];
            unsigned long long bp0 = *reinterpret_cast<unsigned long long*>(&b0.x);
            unsigned long long bp1 = *reinterpret_cast<unsigned long long*>(&b0.z);
            unsigned long long bp2 = *reinterpret_cast<unsigned long long*>(&b1.x);
            unsigned long long bp3 = *reinterpret_cast<unsigned long long*>(&b1.z);

            unsigned long long s;
            s = splat2(a0.x);
            fma2(acc[0][0], s, bp0); fma2(acc[0][1], s, bp1); fma2(acc[0][2], s, bp2); fma2(acc[0][3], s, bp3);
            s = splat2(a0.y);
            fma2(acc[1][0], s, bp0); fma2(acc[1][1], s, bp1); fma2(acc[1][2], s, bp2); fma2(acc[1][3], s, bp3);
            s = splat2(a0.z);
            fma2(acc[2][0], s, bp0); fma2(acc[2][1], s, bp1); fma2(acc[2][2], s, bp2); fma2(acc[2][3], s, bp3);
            s = splat2(a0.w);
            fma2(acc[3][0], s, bp0); fma2(acc[3][1], s, bp1); fma2(acc[3][2], s, bp2); fma2(acc[3][3], s, bp3);
            s = splat2(a1.x);
            fma2(acc[4][0], s, bp0); fma2(acc[4][1], s, bp1); fma2(acc[4][2], s, bp2); fma2(acc[4][3], s, bp3);
            s = splat2(a1.y);
            fma2(acc[5][0], s, bp0); fma2(acc[5][1], s, bp1); fma2(acc[5][2], s, bp2); fma2(acc[5][3], s, bp3);
            s = splat2(a1.z);
            fma2(acc[6][0], s, bp0); fma2(acc[6][1], s, bp1); fma2(acc[6][2], s, bp2); fma2(acc[6][3], s, bp3);
            s = splat2(a1.w);
            fma2(acc[7][0], s, bp0); fma2(acc[7][1], s, bp1); fma2(acc[7][2], s, bp2); fma2(acc[7][3], s, bp3);
        }
        __syncthreads();
    }

    // write C tile: mat[b][n], b = ty*8+i, n = n0 + tx*8 + {0..7}  (g_mat is 16B-aligned)
#pragma unroll
    for (int i = 0; i < 8; i++) {
        const int b = ty * 8 + i;
        float c0, c1, c2, c3, c4, c5, c6, c7;
        asm("mov.b64 {%0,%1}, %2;" : "=f"(c0), "=f"(c1) : "l"(acc[i][0]));
        asm("mov.b64 {%0,%1}, %2;" : "=f"(c2), "=f"(c3) : "l"(acc[i][1]));
        asm("mov.b64 {%0,%1}, %2;" : "=f"(c4), "=f"(c5) : "l"(acc[i][2]));
        asm("mov.b64 {%0,%1}, %2;" : "=f"(c6), "=f"(c7) : "l"(acc[i][3]));
        float* dst = g_mat + (size_t)b * N + n0 + tx * 8;
        *(float4*)(dst)     = make_float4(c0, c1, c2, c3);
        *(float4*)(dst + 4) = make_float4(c4, c5, c6, c7);
    }
}

// ---------------- fused update + exact top-K + loss (unchanged, proven) ----------------
extern "C" __global__ void __launch_bounds__(TPK_THREADS)
topk_update_kernel(const int* __restrict__ indexes, const int* __restrict__ labels,
                   const float* __restrict__ feat, const float* __restrict__ f_weak,
                   float* __restrict__ out, float* __restrict__ outF)
{
    extern __shared__ char dyn[];
    unsigned* skeys = (unsigned*)(dyn + OFF_KEYS);
    unsigned* cbuf[2] = { (unsigned*)(dyn + OFF_CAND0), (unsigned*)(dyn + OFF_CAND1) };
    unsigned* whist = (unsigned*)(dyn + OFF_WHIST);   // [16][256]

    __shared__ unsigned hist[256];
    __shared__ unsigned sfA[256], sfB[256];
    __shared__ float    wpartf[16];
    __shared__ unsigned wsum[16], wbase[16];
    __shared__ int      s_sel, s_kleft, s_total, s_mode;
    __shared__ float    s_pmin, s_nmax, s_inv;

    const int b   = blockIdx.x;
    const int tid = threadIdx.x;
    const int wid = tid >> 5;
    const int lid = tid & 31;
    const int idx = indexes[b];

    // ---------- Part A: momentum update (last-occurrence wins) ----------
    {
        bool last = true;
        for (int j = b + 1; j < GB; j++) if (indexes[j] == idx) last = false;

        const float* fr = feat   + (size_t)idx * GD;
        const float* fw = f_weak + (size_t)b   * GD;
        float ss = 0.f;
        for (int d = tid; d < GD; d += TPK_THREADS) {
            float w = fr[d] * MOMENTUM + fw[d] * (1.0f - MOMENTUM);
            ss += w * w;
        }
        ss = wred_add(ss);
        if (lid == 0) wpartf[wid] = ss;
        __syncthreads();
        if (tid == 0) {
            float t = 0.f;
            for (int w = 0; w < 16; w++) t += wpartf[w];
            s_inv = 1.0f / fmaxf(sqrtf(t), NEPS);
        }
        __syncthreads();
        if (last) {
            const float inv = s_inv;
            float* dst = outF + (size_t)idx * GD;
            for (int d = tid; d < GD; d += TPK_THREADS) {
                float w = fr[d] * MOMENTUM + fw[d] * (1.0f - MOMENTUM);
                dst[d] = w * inv;
            }
        }
    }
    __syncthreads();

    // ---------- Part B: build keys, reduce pmin / nmax ----------
    const int mylab = labels[idx];
    const float* row = g_mat + (size_t)b * GN;

    float pmin = INFINITY, nmax = -INFINITY;
    for (int n = tid; n < GN; n += TPK_THREADS) {
        float s = row[n];
        unsigned u = __float_as_uint(s);
        unsigned key = (u & 0x80000000u) ? ~u : (u | 0x80000000u);
        if (labels[n] == mylab) { key = 0u; pmin = fminf(pmin, s); }
        else                    { nmax = fmaxf(nmax, s); }
        skeys[n] = key;
    }
    pmin = wred_min(pmin);
    nmax = wred_max(nmax);
    if (lid == 0) wpartf[wid] = pmin;
    __syncthreads();
    if (tid == 0) {
        float t = INFINITY;
        for (int w = 0; w < 16; w++) t = fminf(t, wpartf[w]);
        s_pmin = t;
    }
    __syncthreads();
    if (lid == 0) wpartf[wid] = nmax;
    __syncthreads();
    if (tid == 0) {
        float t = -INFINITY;
        for (int w = 0; w < 16; w++) t = fmaxf(t, wpartf[w]);
        s_nmax = t;
        s_kleft = KSEL;
        s_mode = 0;
        s_total = 0;
    }
    __syncthreads();

    const float m = fmaxf(s_nmax, s_pmin);
    float lsum = 0.f;

    unsigned prefix = 0, pmask = 0;
    int cur = 0;

    for (int p = 0; p < 4; p++) {
        const int shift = 24 - 8 * p;
        const int mode  = s_mode;
        const int ncand = s_total;
        const unsigned* src = cbuf[cur];

        for (int i = tid; i < 16 * 256; i += TPK_THREADS) whist[i] = 0u;
        __syncthreads();

        // phase 1: histogram
        if (mode) {
            for (int i = tid; i < ncand; i += TPK_THREADS)
                atomicAdd(&whist[wid * 256 + ((src[i] >> shift) & 255u)], 1u);
        } else {
            for (int n = tid; n < GN; n += TPK_THREADS) {
                unsigned k = skeys[n];
                if ((k & pmask) == prefix)
                    atomicAdd(&whist[wid * 256 + ((k >> shift) & 255u)], 1u);
            }
        }
        __syncthreads();

        if (tid < 256) {
            unsigned t = 0;
#pragma unroll
            for (int w = 0; w < 16; w++) t += whist[w * 256 + tid];
            hist[tid] = t;
            sfA[tid] = t;
        }
        __syncthreads();

        // inclusive suffix sums (8 ping-pong steps)
        {
            unsigned* sA = sfA; unsigned* sB = sfB;
#pragma unroll
            for (int off = 1; off < 256; off <<= 1) {
                if (tid < 256) sB[tid] = sA[tid] + ((tid + off < 256) ? sA[tid + off] : 0u);
                __syncthreads();
                unsigned* t = sA; sA = sB; sB = t;
            }
        }

        {
            const int kleft = s_kleft;
            if (tid < 256) {
                unsigned ge = sfA[tid];
                unsigned gt = (tid < 255) ? sfA[tid + 1] : 0u;
                if ((int)gt < kleft && (int)ge >= kleft) {
                    s_sel = tid;
                    s_kleft = kleft - (int)gt;
                }
            }
        }
        __syncthreads();
        const unsigned sel = (unsigned)s_sel;

        // phase 2: count matches (bin == sel)
        int mc = 0;
        if (mode) {
            for (int i = tid; i < ncand; i += TPK_THREADS)
                if (((src[i] >> shift) & 255u) == sel) mc++;
        } else {
            for (int n = tid; n < GN; n += TPK_THREADS) {
                unsigned k = skeys[n];
                if ((k & pmask) == prefix && ((k >> shift) & 255u) == sel) mc++;
            }
        }

        unsigned x = (unsigned)mc;
#pragma unroll
        for (int off = 1; off < 32; off <<= 1) {
            unsigned y = __shfl_up_sync(0xffffffffu, x, off);
            if (lid >= off) x += y;
        }
        if (lid == 31) wsum[wid] = x;
        __syncthreads();
        if (wid == 0 && lid < 16) {
            unsigned t = wsum[lid];
#pragma unroll
            for (int off = 1; off < 16; off <<= 1) {
                unsigned y = __shfl_up_sync(0x0000ffffu, t, off);
                if (lid >= off) t += y;
            }
            wbase[lid] = t - wsum[lid];
            if (lid == 15) s_total = (int)t;
        }
        __syncthreads();
        unsigned myoff = wbase[wid] + (x - (unsigned)mc);
        const int total = s_total;
        const int doEmit = (p < 3) && (total <= CAP);

        unsigned* dstc = cbuf[cur ^ 1];
        if (mode) {
            for (int i = tid; i < ncand; i += TPK_THREADS) {
                unsigned k = src[i];
                unsigned bin = (k >> shift) & 255u;
                if (bin > sel) lsum += __expf((keyval(k) - m) * INV_TEMP);
                else if (bin == sel && doEmit) dstc[myoff++] = k;
            }
        } else {
            for (int n = tid; n < GN; n += TPK_THREADS) {
                unsigned k = skeys[n];
                if ((k & pmask) != prefix) continue;
                unsigned bin = (k >> shift) & 255u;
                if (bin > sel) lsum += __expf((keyval(k) - m) * INV_TEMP);
                else if (bin == sel && doEmit) dstc[myoff++] = k;
            }
        }
        __syncthreads();

        prefix |= sel << shift;
        pmask  |= 255u << shift;
        if (doEmit) { cur ^= 1; if (tid == 0) s_mode = 1; }
        else if (tid == 0) { s_total = 0; }
        __syncthreads();
    }

    const unsigned T = prefix;
    const int kleft = s_kleft;

    lsum = wred_add(lsum);
    if (lid == 0) wpartf[wid] = lsum;
    __syncthreads();
    if (tid == 0) {
        float tot = 0.f;
        for (int w = 0; w < 16; w++) tot += wpartf[w];
        tot += (float)kleft * __expf((keyval(T) - m) * INV_TEMP);
        tot += __expf((s_pmin - m) * INV_TEMP);
        float loss_b = (logf(tot) + m * INV_TEMP) - s_pmin * INV_TEMP;
        g_loss[b] = loss_b;
        __threadfence();
        unsigned ticket = atomicAdd(&g_cnt, 1u);
        if (ticket == gridDim.x - 1) {
            float t = 0.f;
            for (int i = 0; i < GB; i++) t += g_loss[i];
            out[0] = t / (float)GB;
            g_cnt = 0;
        }
    }
}

// ---------------- launch ----------------
extern "C" void kernel_launch(void* const* d_in, const int* in_sizes, int n_in,
                              void* d_out, int out_size)
{
    const float* f      = (const float*)d_in[0];
    const float* f_weak = (const float*)d_in[1];
    const int*   idx    = (const int*)  d_in[2];
    const float* feat   = (const float*)d_in[3];
    const int*   labels = (const int*)  d_in[4];

    const int B = in_sizes[2];               // 64
    const int D = in_sizes[0] / B;           // 2048
    const int N = in_sizes[4];               // 16384

    float* out  = (float*)d_out;
    float* outF = out + 1;                   // [loss, updated_features...] (4B-aligned only!)

    gemm_copy_kernel<<<N / BN2, 128>>>(f, feat, outF, N, D);

    cudaFuncSetAttribute(topk_update_kernel,
                         cudaFuncAttributeMaxDynamicSharedMemorySize, TPK_SMEM);
    topk_update_kernel<<<B, TPK_THREADS, TPK_SMEM>>>(idx, labels, feat, f_weak, out, outF);
}